// round 6
// baseline (speedup 1.0000x reference)
#include <cuda_runtime.h>
#include <cuda_bf16.h>
#include <cstdint>

// NCE loss (training branch, size_average=True).
// N=4096, E=1024, V=50257, K=25.
// One CTA per row n; 8 warps; each warp streams its 3-4 candidate weight rows
// through a private 2-stage x 4KB SMEM double buffer via cp.async (LDGSTS),
// overlapping DRAM fetch with the previous row's dot product. x[n] is held in
// registers (8 x float4 per lane). No block barriers in the mainloop: each
// lane reads back exactly the bytes its own cp.asyncs wrote, so
// cp.async.wait_group alone gives the needed visibility.

#define THREADS   256
#define NWARP     8
#define MAXD      4          // ceil(26/8)
#define ROW_BYTES 4096       // E=1024 floats
#define SMEM_BYTES (NWARP * 2 * ROW_BYTES)   // 64 KB

__device__ __forceinline__ void cp16(uint32_t dst, const void* src) {
    asm volatile("cp.async.cg.shared.global [%0], [%1], 16;\n" :: "r"(dst), "l"(src));
}
__device__ __forceinline__ void cp_commit() {
    asm volatile("cp.async.commit_group;\n" ::: "memory");
}
template<int P> __device__ __forceinline__ void cp_wait() {
    asm volatile("cp.async.wait_group %0;\n" :: "n"(P) : "memory");
}

__global__ void __launch_bounds__(THREADS, 3)
nce_main(const float* __restrict__ x,
         const int*   __restrict__ target,
         const int*   __restrict__ noise_idx,
         const float* __restrict__ weight,
         const float* __restrict__ bias,
         const float* __restrict__ noise,
         float* __restrict__ out,
         int N, int E, int K)
{
    extern __shared__ float smem_buf[];              // [NWARP][2][1024]

    const int n    = blockIdx.x;
    const int tid  = threadIdx.x;
    const int lane = tid & 31;
    const int wid  = tid >> 5;
    const int nk   = K + 1;                          // 26

    uint32_t sbase;
    asm("{ .reg .u64 t; cvta.to.shared.u64 t, %1; cvt.u32.u64 %0, t; }"
        : "=r"(sbase) : "l"(smem_buf));
    const uint32_t wbase = sbase + (uint32_t)(wid * 2 * ROW_BYTES) + (uint32_t)(lane * 16);

    // x[n] slice in registers: xv[j] pairs with weight bytes at lane*16 + j*512
    float4 xv[8];
    const float4* x4 = reinterpret_cast<const float4*>(x + (size_t)n * E);
    #pragma unroll
    for (int j = 0; j < 8; j++) xv[j] = __ldg(&x4[lane + 32 * j]);

    // This warp's candidate list + indices (uniform loads, issued together)
    int myk[MAXD], myidx[MAXD], nd = 0;
    #pragma unroll
    for (int k = wid; k < nk; k += NWARP) { myk[nd] = k; nd++; }
    #pragma unroll
    for (int i = 0; i < MAXD; i++) {
        if (i < nd) {
            const int k = myk[i];
            myidx[i] = (k == 0) ? __ldg(&target[n]) : __ldg(&noise_idx[n * K + (k - 1)]);
        }
    }

    // Prefetch row i into stage s (8 x 16B per lane)
    auto prefetch = [&](int i, int s) {
        const char* src = reinterpret_cast<const char*>(weight + (size_t)myidx[i] * E)
                          + lane * 16;
        const uint32_t dst = wbase + (uint32_t)(s * ROW_BYTES);
        #pragma unroll
        for (int j = 0; j < 8; j++) cp16(dst + j * 512, src + j * 512);
        cp_commit();
    };

    if (nd > 0) prefetch(0, 0);
    if (nd > 1) prefetch(1, 1);

    float loss = 0.0f;
    for (int i = 0; i < nd; i++) {
        // Ensure dot i's group is complete (at most the newest group may pend)
        if (i + 1 < nd) cp_wait<1>(); else cp_wait<0>();

        const float4* wb = reinterpret_cast<const float4*>(
            smem_buf + (wid * 2 + (i & 1)) * (ROW_BYTES / 4));
        float s = 0.0f;
        #pragma unroll
        for (int j = 0; j < 8; j++) {
            const float4 wv = wb[lane + 32 * j];
            s += wv.x * xv[j].x + wv.y * xv[j].y + wv.z * xv[j].z + wv.w * xv[j].w;
        }

        // Refill this stage for dot i+2 (safe: compute of dot i just consumed it)
        if (i + 2 < nd) prefetch(i + 2, i & 1);

        #pragma unroll
        for (int o = 16; o; o >>= 1)
            s += __shfl_xor_sync(0xffffffffu, s, o);

        if (lane == 0) {
            const int   k     = myk[i];
            const int   idx   = myidx[i];
            const float logit = s + __ldg(&bias[idx]);
            const float p     = __expf(logit - 9.0f);
            const float kpn   = 25.0f * __ldg(&noise[idx]);
            const float num   = (k == 0) ? p : kpn;
            loss += __logf(num / (p + kpn));
        }
    }

    // Per-warp scalar on lane 0 -> tiny smem combine -> one atomic per CTA
    __shared__ float wloss[NWARP];
    if (lane == 0) wloss[wid] = loss;
    __syncthreads();
    if (tid == 0) {
        float t = 0.0f;
        #pragma unroll
        for (int w = 0; w < NWARP; w++) t += wloss[w];
        atomicAdd(out, -t / (float)N);
    }
}

extern "C" void kernel_launch(void* const* d_in, const int* in_sizes, int n_in,
                              void* d_out, int out_size)
{
    const float* x         = (const float*)d_in[0];
    const int*   target    = (const int*)  d_in[1];
    const int*   noise_idx = (const int*)  d_in[2];
    const float* weight    = (const float*)d_in[3];
    const float* bias      = (const float*)d_in[4];
    const float* noise     = (const float*)d_in[5];

    const int N = in_sizes[1];            // 4096
    const int E = in_sizes[0] / N;        // 1024
    const int K = in_sizes[2] / N;        // 25

    static int smem_set = 0;
    if (!smem_set) {
        cudaFuncSetAttribute(nce_main, cudaFuncAttributeMaxDynamicSharedMemorySize,
                             SMEM_BYTES);
        smem_set = 1;
    }

    cudaMemsetAsync(d_out, 0, sizeof(float));
    nce_main<<<N, THREADS, SMEM_BYTES>>>(x, target, noise_idx, weight, bias, noise,
                                         (float*)d_out, N, E, K);
}

// round 7
// speedup vs baseline: 1.1778x; 1.1778x over previous
#include <cuda_runtime.h>
#include <cuda_bf16.h>
#include <cstdint>

// NCE loss (training branch, size_average=True).
// N=4096, E=1024, V=50257, K=25.
// Persistent kernel: 1184 CTAs (8/SM x 148 SMs), each grid-strides over rows.
// Per row: 8 warps x 3-4 dot products, 8 independent LDG.128 per lane.
// x[n] double-buffered in SMEM via cp.async so the next row's x-load
// overlaps the current row's dots. One atomic per CTA at the end.

#define THREADS 256
#define NWARP   8
#define GRID    1184          // 148 SMs * 8 CTAs

__device__ __forceinline__ void cp16(uint32_t dst, const void* src) {
    asm volatile("cp.async.cg.shared.global [%0], [%1], 16;\n" :: "r"(dst), "l"(src));
}
__device__ __forceinline__ void cp_commit() {
    asm volatile("cp.async.commit_group;\n" ::: "memory");
}
__device__ __forceinline__ void cp_wait0() {
    asm volatile("cp.async.wait_group 0;\n" ::: "memory");
}

__global__ __launch_bounds__(THREADS, 8)
void nce_main(const float* __restrict__ x,
              const int*   __restrict__ target,
              const int*   __restrict__ noise_idx,
              const float* __restrict__ weight,
              const float* __restrict__ bias,
              const float* __restrict__ noise,
              float* __restrict__ out,
              int N, int E, int K)
{
    const int tid  = threadIdx.x;
    const int lane = tid & 31;
    const int wid  = tid >> 5;
    const int nk   = K + 1;                // 26

    __shared__ float4 xs[2][256];          // double-buffered x row
    __shared__ float  wloss[NWARP];

    uint32_t xs_addr[2];
    {
        uint32_t base;
        asm("{ .reg .u64 t; cvta.to.shared.u64 t, %1; cvt.u32.u64 %0, t; }"
            : "=r"(base) : "l"(&xs[0][0]));
        xs_addr[0] = base + tid * 16;
        xs_addr[1] = base + 4096 + tid * 16;
    }

    // Prime buffer 0 with the first row's x
    int n0 = blockIdx.x;
    if (n0 < N) {
        cp16(xs_addr[0], (const char*)(x + (size_t)n0 * E) + tid * 16);
        cp_commit();
    }

    float loss = 0.0f;                     // warp-local (lane 0) across all rows
    int buf = 0;

    for (int n = n0; n < N; n += GRID, buf ^= 1) {
        // Start streaming the NEXT row's x into the other buffer
        const int n_next = n + GRID;
        if (n_next < N) {
            cp16(xs_addr[buf ^ 1], (const char*)(x + (size_t)n_next * E) + tid * 16);
            cp_commit();
        }
        // Wait for THIS row's x (all groups except possibly the one just issued)
        if (n_next < N) {
            asm volatile("cp.async.wait_group 1;\n" ::: "memory");
        } else {
            cp_wait0();
        }
        __syncthreads();

        const float4* xb = xs[buf];

        for (int k = wid; k < nk; k += NWARP) {
            const int idx = (k == 0) ? target[n] : noise_idx[n * K + (k - 1)];
            const float4* wrow = reinterpret_cast<const float4*>(weight + (size_t)idx * E);

            float s = 0.0f;
            #pragma unroll
            for (int j = 0; j < 8; j++) {   // 8 independent LDG.128 per lane
                const float4 wv = __ldg(&wrow[lane + 32 * j]);
                const float4 xv = xb[lane + 32 * j];
                s += wv.x * xv.x + wv.y * xv.y + wv.z * xv.z + wv.w * xv.w;
            }
            #pragma unroll
            for (int o = 16; o; o >>= 1)
                s += __shfl_xor_sync(0xffffffffu, s, o);

            if (lane == 0) {
                const float logit = s + __ldg(&bias[idx]);
                const float p     = __expf(logit - 9.0f);
                const float kpn   = 25.0f * __ldg(&noise[idx]);
                const float num   = (k == 0) ? p : kpn;
                loss += __logf(num / (p + kpn));
            }
        }
        __syncthreads();   // all warps done with xs[buf] before it is refilled
    }

    if (lane == 0) wloss[wid] = loss;
    __syncthreads();
    if (tid == 0) {
        float t = 0.0f;
        #pragma unroll
        for (int w = 0; w < NWARP; w++) t += wloss[w];
        atomicAdd(out, -t / (float)N);     // one atomic per CTA
    }
}

extern "C" void kernel_launch(void* const* d_in, const int* in_sizes, int n_in,
                              void* d_out, int out_size)
{
    const float* x         = (const float*)d_in[0];
    const int*   target    = (const int*)  d_in[1];
    const int*   noise_idx = (const int*)  d_in[2];
    const float* weight    = (const float*)d_in[3];
    const float* bias      = (const float*)d_in[4];
    const float* noise     = (const float*)d_in[5];

    const int N = in_sizes[1];            // 4096
    const int E = in_sizes[0] / N;        // 1024
    const int K = in_sizes[2] / N;        // 25

    cudaMemsetAsync(d_out, 0, sizeof(float));
    nce_main<<<GRID, THREADS>>>(x, target, noise_idx, weight, bias, noise,
                                (float*)d_out, N, E, K);
}